// round 6
// baseline (speedup 1.0000x reference)
#include <cuda_runtime.h>
#include <cuda_bf16.h>
#include <math.h>

#define LSEQ 512
#define DM   192
#define DI   384
#define NS   16
#define RK   12
#define XO   44      // RK + 2*NS
#define NLAY 24
#define NCH  32
#define CS   16      // LSEQ / NCH

// ---------------- scratch (static device globals; no runtime allocation) ----------------
__device__ float g_hidden[LSEQ * DM];
__device__ float g_resid[2][LSEQ * DM];          // ping-pong
__device__ float g_xz[LSEQ * 2 * DI];
__device__ float g_u[2][LSEQ * DI];
__device__ float g_du[2][LSEQ * DI];
__device__ float g_dtv[2][LSEQ * DI];
__device__ float g_rex[2][LSEQ * DI];
__device__ float g_z[2][LSEQ * DI];
__device__ float g_Bm[2][LSEQ * NS];
__device__ float g_Cm[2][LSEQ * NS];
__device__ float g_PA[2][NCH * NS * DI];
__device__ float g_HE[2][NCH * NS * DI];
__device__ float g_y[2][LSEQ * DI];
// patch-embed scratch
__device__ float g_xpatch[LSEQ * 4096];          // gathered patches, 8 MB
__device__ float g_ppart[8 * LSEQ * DM];         // split-K partials, 3 MB
// preprocessed weights
__device__ float g_inT[NLAY * DM * 2 * DI];      // [l][k][o]
__device__ float g_outT[NLAY * DI * DM];         // [l][d][c]
__device__ float g_xpT[2][NLAY * DI * XO];       // [l][d][o]
__device__ float g_dtT[2][NLAY * RK * DI];       // [l][r][d]
__device__ float g_base[2][NLAY * DI];           // A0 = -exp(Alog[...,0])
__device__ float g_delta[2][NLAY * NS * DI];     // An - (n+1)*A0, [l][n][d]
__device__ float g_Dva[2][NLAY * DI];

// ---------------- setup: weight transposes + A-derived + zero resid ----------------
__global__ void k_setup(const float* __restrict__ in_w, const float* __restrict__ out_w,
                        const float* __restrict__ xpf, const float* __restrict__ xpb,
                        const float* __restrict__ dtfw, const float* __restrict__ dtbw,
                        const float* __restrict__ Alog_f, const float* __restrict__ Alog_b,
                        const float* __restrict__ D_f, const float* __restrict__ D_b) {
    int tid = blockIdx.x * blockDim.x + threadIdx.x;
    int nth = gridDim.x * blockDim.x;
    // in_w (24,768,192) -> [l][k][o]
    for (int i = tid; i < NLAY * 768 * DM; i += nth) {
        int l = i / (768 * DM); int r = i % (768 * DM); int o = r / DM; int k = r % DM;
        g_inT[(l * DM + k) * 768 + o] = in_w[i];
    }
    // out_w (24,192,384) -> [l][d][c]
    for (int i = tid; i < NLAY * DM * DI; i += nth) {
        int l = i / (DM * DI); int r = i % (DM * DI); int c = r / DI; int d = r % DI;
        g_outT[(l * DI + d) * DM + c] = out_w[i];
    }
    // xp (24,44,384) -> [l][d][o]
    for (int i = tid; i < NLAY * XO * DI; i += nth) {
        int l = i / (XO * DI); int r = i % (XO * DI); int o = r / DI; int d = r % DI;
        g_xpT[0][(l * DI + d) * XO + o] = xpf[i];
        g_xpT[1][(l * DI + d) * XO + o] = xpb[i];
    }
    // dt_w (24,384,12) -> [l][r][d]
    for (int i = tid; i < NLAY * DI * RK; i += nth) {
        int l = i / (DI * RK); int r2 = i % (DI * RK); int d = r2 / RK; int rr = r2 % RK;
        g_dtT[0][(l * RK + rr) * DI + d] = dtfw[i];
        g_dtT[1][(l * RK + rr) * DI + d] = dtbw[i];
    }
    // A-derived per (l,d)
    for (int i = tid; i < NLAY * DI; i += nth) {
        int l = i / DI; int d = i % DI;
        for (int dir = 0; dir < 2; dir++) {
            const float* Alog = dir ? Alog_b : Alog_f;
            float A0 = -expf(Alog[i * NS + 0]);
            g_base[dir][i] = A0;
            for (int n = 0; n < NS; n++) {
                float An = -expf(Alog[i * NS + n]);
                g_delta[dir][(l * NS + n) * DI + d] = An - (float)(n + 1) * A0;
            }
        }
        g_Dva[0][i] = D_f[i];
        g_Dva[1][i] = D_b[i];
    }
    for (int i = tid; i < LSEQ * DM; i += nth) g_resid[0][i] = 0.f;
}

// ---------------- patch embed: gather 16^3 patches -> [512][4096] ----------------
__global__ void k_gather(const float* __restrict__ x) {
    int i = blockIdx.x * blockDim.x + threadIdx.x;
    int nth = gridDim.x * blockDim.x;
    for (; i < LSEQ * 4096; i += nth) {
        int p = i >> 12;
        int k = i & 4095;
        int pz = p >> 6, py = (p >> 3) & 7, px = p & 7;
        int dz = k >> 8, dy = (k >> 4) & 15, dx = k & 15;
        size_t src = ((size_t)(pz * 16 + dz) * 128 + (py * 16 + dy)) * 128 + (px * 16 + dx);
        g_xpatch[i] = x[src];
    }
}

// ---------------- patch embed: split-K GEMM [512,4096]@[4096,192] ----------------
// grid (8 patch-tiles, 3 chan-tiles, 8 k-splits); 256 threads; 64x64 tile, K-slice 512
__global__ void k_patch_gemm(const float* __restrict__ pw) {
    __shared__ float sA[64][65];
    __shared__ float sB[64][65];
    int p0 = blockIdx.x * 64;
    int c0 = blockIdx.y * 64;
    int ks = blockIdx.z;
    int tid = threadIdx.x;
    int tr = tid >> 4, tc = tid & 15;
    float acc[4][4] = {};
    for (int kt = 0; kt < 8; kt++) {
        int kb = ks * 512 + kt * 64;
        int kk = tid & 63;
        int r0 = tid >> 6;
        for (int r = r0; r < 64; r += 4) {
            sA[r][kk] = g_xpatch[(size_t)(p0 + r) * 4096 + kb + kk];
            sB[kk][r] = pw[(size_t)(c0 + r) * 4096 + kb + kk];
        }
        __syncthreads();
        for (int q = 0; q < 64; q++) {
            float a[4], b[4];
#pragma unroll
            for (int i = 0; i < 4; i++) a[i] = sA[tr * 4 + i][q];
#pragma unroll
            for (int j = 0; j < 4; j++) b[j] = sB[q][tc * 4 + j];
#pragma unroll
            for (int i = 0; i < 4; i++)
#pragma unroll
                for (int j = 0; j < 4; j++)
                    acc[i][j] = fmaf(a[i], b[j], acc[i][j]);
        }
        __syncthreads();
    }
#pragma unroll
    for (int i = 0; i < 4; i++)
#pragma unroll
        for (int j = 0; j < 4; j++)
            g_ppart[((size_t)ks * LSEQ + p0 + tr * 4 + i) * DM + c0 + tc * 4 + j] = acc[i][j];
}

__global__ void k_patch_reduce(const float* __restrict__ pb) {
    int i = blockIdx.x * blockDim.x + threadIdx.x;
    if (i >= LSEQ * DM) return;
    int c = i % DM;
    float s = pb[c];
#pragma unroll
    for (int ks = 0; ks < 8; ks++) s += g_ppart[(size_t)ks * LSEQ * DM + i];
    g_hidden[i] = s;
}

// ---------------- per layer: residual + LN + inproj GEMM ----------------
// grid 128 = 32 token-groups(16) x 4 out-groups(192); 256 threads
__global__ void k_layer_in(int l, const float* __restrict__ ln_w, const float* __restrict__ ln_b) {
    __shared__ float shn[16][DM];
    __shared__ float sr1[16][16];
    __shared__ float sr2[16][16];
    __shared__ float sstat[16][2];
    int bx = blockIdx.x;
    int tg = bx & 31, og = bx >> 5;
    int t0 = tg * 16;
    int tid = threadIdx.x;
    int rb = l & 1;
    const float* rsrc = g_resid[rb];
    float* rdst = g_resid[rb ^ 1];
    for (int i = tid; i < 16 * DM; i += 256) {
        int tt = i / DM, c = i % DM;
        float r = rsrc[(t0 + tt) * DM + c] + g_hidden[(t0 + tt) * DM + c];
        shn[tt][c] = r;
        if (og == 0) rdst[(t0 + tt) * DM + c] = r;
    }
    __syncthreads();
    {
        int tt = tid >> 4, seg = tid & 15;
        float s = 0.f, s2 = 0.f;
#pragma unroll
        for (int j = 0; j < 12; j++) {
            float v = shn[tt][seg * 12 + j];
            s += v; s2 += v * v;
        }
        sr1[tt][seg] = s; sr2[tt][seg] = s2;
    }
    __syncthreads();
    if (tid < 16) {
        float s = 0.f, s2 = 0.f;
#pragma unroll
        for (int j = 0; j < 16; j++) { s += sr1[tid][j]; s2 += sr2[tid][j]; }
        float m = s / DM;
        sstat[tid][0] = m;
        sstat[tid][1] = rsqrtf(s2 / DM - m * m + 1e-5f);
    }
    __syncthreads();
    for (int i = tid; i < 16 * DM; i += 256) {
        int tt = i / DM, c = i % DM;
        shn[tt][c] = (shn[tt][c] - sstat[tt][0]) * sstat[tt][1] * ln_w[l * DM + c] + ln_b[l * DM + c];
    }
    __syncthreads();
    int o64 = tid & 63;
    int ti = tid >> 6;  // 4 tokens each
    const float* wbase = g_inT + (size_t)(l * DM) * 768 + og * 192 + o64;
    float acc[4][3] = {};
    for (int k = 0; k < DM; k++) {
        const float* wk = wbase + (size_t)k * 768;
        float w0 = wk[0], w1 = wk[64], w2 = wk[128];
#pragma unroll
        for (int i2 = 0; i2 < 4; i2++) {
            float xv = shn[ti * 4 + i2][k];
            acc[i2][0] = fmaf(xv, w0, acc[i2][0]);
            acc[i2][1] = fmaf(xv, w1, acc[i2][1]);
            acc[i2][2] = fmaf(xv, w2, acc[i2][2]);
        }
    }
#pragma unroll
    for (int i2 = 0; i2 < 4; i2++) {
        int t = t0 + ti * 4 + i2;
        int ob = og * 192 + o64;
        g_xz[t * 768 + ob] = acc[i2][0];
        g_xz[t * 768 + ob + 64] = acc[i2][1];
        g_xz[t * 768 + ob + 128] = acc[i2][2];
    }
}

// ---------------- per layer: conv + silu + xproj + dtproj + rexp ----------------
// grid 1024 = 2 dirs x 512 scan-time tokens; 128 threads
__global__ void k_conv_proj(int l,
                            const float* __restrict__ cfw, const float* __restrict__ cfb,
                            const float* __restrict__ cbw, const float* __restrict__ cbb,
                            const float* __restrict__ dtbf, const float* __restrict__ dtbb) {
    __shared__ float su[DI];
    __shared__ float spart[2][XO];
    __shared__ float sdbl[XO];
    int dir = blockIdx.x >> 9;
    int t = blockIdx.x & 511;
    int s = dir ? (LSEQ - 1 - t) : t;
    const float* cw = dir ? cbw : cfw;
    const float* cb = dir ? cbb : cfb;
    const float* dtb = dir ? dtbb : dtbf;
    int tid = threadIdx.x;
    for (int d = tid; d < DI; d += 128) {
        float acc = cb[l * DI + d];
#pragma unroll
        for (int j = 0; j < 4; j++) {
            int ts = t - 3 + j;
            if (ts >= 0) {
                int orig = dir ? (LSEQ - 1 - ts) : ts;
                acc = fmaf(g_xz[orig * 768 + d], cw[(l * DI + d) * 4 + j], acc);
            }
        }
        float u = acc / (1.f + __expf(-acc));
        su[d] = u;
        g_u[dir][t * DI + d] = u;
        g_z[dir][t * DI + d] = g_xz[s * 768 + DI + d];
    }
    __syncthreads();
    if (tid < 88) {
        int half = tid / XO;
        int o = tid - half * XO;
        const float* xp = g_xpT[dir] + (size_t)(l * DI) * XO + o;
        float acc = 0.f;
        int d0 = half * 192;
#pragma unroll 4
        for (int d = d0; d < d0 + 192; d++) acc = fmaf(su[d], xp[(size_t)d * XO], acc);
        spart[half][o] = acc;
    }
    __syncthreads();
    if (tid < XO) sdbl[tid] = spart[0][tid] + spart[1][tid];
    __syncthreads();
    if (tid < NS) {
        g_Bm[dir][t * NS + tid] = sdbl[RK + tid];
        g_Cm[dir][t * NS + tid] = sdbl[RK + NS + tid];
    }
    for (int d = tid; d < DI; d += 128) {
        float a = dtb[l * DI + d];
        const float* dw = g_dtT[dir] + (size_t)(l * RK) * DI + d;
#pragma unroll
        for (int r = 0; r < RK; r++) a = fmaf(sdbl[r], dw[(size_t)r * DI], a);
        float dt = (a > 15.f) ? a : log1pf(__expf(a));
        g_dtv[dir][t * DI + d] = dt;
        g_du[dir][t * DI + d] = dt * su[d];
        g_rex[dir][t * DI + d] = __expf(dt * g_base[dir][l * DI + d]);
    }
}

// ---------------- per layer: chunk-local scan (produces carries) ----------------
// grid 128 = 2 dirs x 32 chunks x 2 d-halves; 192 threads (one per d)
__global__ void k_scan_local(int l) {
    __shared__ float sB[CS * NS];
    int bx = blockIdx.x;
    int dir = bx & 1;
    int c = (bx >> 1) & 31;
    int dh = bx >> 6;
    int tid = threadIdx.x;
    int d = dh * 192 + tid;
    for (int i = tid; i < CS * NS; i += 192) sB[i] = g_Bm[dir][c * CS * NS + i];
    __syncthreads();
    float delta[NS];
#pragma unroll
    for (int n = 0; n < NS; n++) delta[n] = g_delta[dir][(l * NS + n) * DI + d];
    float h[NS], pa[NS];
#pragma unroll
    for (int n = 0; n < NS; n++) { h[n] = 0.f; pa[n] = 1.f; }
    for (int i = 0; i < CS; i++) {
        int tg = c * CS + i;
        float du = g_du[dir][tg * DI + d];
        float r = g_rex[dir][tg * DI + d];
        float dt = g_dtv[dir][tg * DI + d];
        float p = 1.f;
#pragma unroll
        for (int n = 0; n < NS; n++) {
            p *= r;
            float dA = p * fmaf(dt, delta[n], 1.f);
            pa[n] *= dA;
            h[n] = fmaf(dA, h[n], du * sB[i * NS + n]);
        }
    }
#pragma unroll
    for (int n = 0; n < NS; n++) {
        g_PA[dir][(c * NS + n) * DI + d] = pa[n];
        g_HE[dir][(c * NS + n) * DI + d] = h[n];
    }
}

// ---------------- per layer: carry combine + apply + y + gate ----------------
__global__ void k_scan_apply(int l) {
    __shared__ float sB[CS * NS], sC[CS * NS];
    int bx = blockIdx.x;
    int dir = bx & 1;
    int c = (bx >> 1) & 31;
    int dh = bx >> 6;
    int tid = threadIdx.x;
    int d = dh * 192 + tid;
    for (int i = tid; i < CS * NS; i += 192) {
        sB[i] = g_Bm[dir][c * CS * NS + i];
        sC[i] = g_Cm[dir][c * CS * NS + i];
    }
    __syncthreads();
    float delta[NS];
#pragma unroll
    for (int n = 0; n < NS; n++) delta[n] = g_delta[dir][(l * NS + n) * DI + d];
    float Dv = g_Dva[dir][l * DI + d];
    float h[NS];
#pragma unroll
    for (int n = 0; n < NS; n++) h[n] = 0.f;
    for (int cp = 0; cp < c; cp++) {
#pragma unroll
        for (int n = 0; n < NS; n++)
            h[n] = fmaf(g_PA[dir][(cp * NS + n) * DI + d], h[n],
                        g_HE[dir][(cp * NS + n) * DI + d]);
    }
    for (int i = 0; i < CS; i++) {
        int tg = c * CS + i;
        float du = g_du[dir][tg * DI + d];
        float r = g_rex[dir][tg * DI + d];
        float dt = g_dtv[dir][tg * DI + d];
        float u = g_u[dir][tg * DI + d];
        float z = g_z[dir][tg * DI + d];
        float p = 1.f, y = 0.f;
#pragma unroll
        for (int n = 0; n < NS; n++) {
            p *= r;
            float dA = p * fmaf(dt, delta[n], 1.f);
            h[n] = fmaf(dA, h[n], du * sB[i * NS + n]);
            y = fmaf(h[n], sC[i * NS + n], y);
        }
        y = fmaf(u, Dv, y);
        float sg = z / (1.f + __expf(-z));
        g_y[dir][tg * DI + d] = y * sg;
    }
}

// ---------------- per layer: out projection -> hidden ----------------
// grid 128 (4 tokens each); 256 threads
__global__ void k_out(int l) {
    __shared__ float sy[4][DI];
    int t0 = blockIdx.x * 4;
    int tid = threadIdx.x;
    for (int i = tid; i < 4 * DI; i += 256) {
        int tt = i / DI, d = i % DI;
        // yb was computed in scan-time (flipped); flip back
        sy[tt][d] = g_y[0][(t0 + tt) * DI + d] + g_y[1][(LSEQ - 1 - (t0 + tt)) * DI + d];
    }
    __syncthreads();
    if (tid < DM) {
        float acc[4] = {};
        const float* wb = g_outT + (size_t)(l * DI) * DM + tid;
        for (int k = 0; k < DI; k++) {
            float w = wb[(size_t)k * DM];
#pragma unroll
            for (int tt = 0; tt < 4; tt++) acc[tt] = fmaf(sy[tt][k], w, acc[tt]);
        }
#pragma unroll
        for (int tt = 0; tt < 4; tt++) g_hidden[(t0 + tt) * DM + tid] = acc[tt];
    }
}

// ---------------- final: LN(resid+hidden)[511] @ head ----------------
__global__ void k_final(const float* __restrict__ nfw, const float* __restrict__ nfb,
                        const float* __restrict__ hw, const float* __restrict__ hb,
                        float* __restrict__ out) {
    __shared__ float sv[DM];
    __shared__ float red1[32], red2[32];
    __shared__ float stat[2];
    int tid = threadIdx.x;
    float v = g_resid[0][511 * DM + tid] + g_hidden[511 * DM + tid];
    sv[tid] = v;
    __syncthreads();
    if (tid < 32) {
        float s = 0.f, s2 = 0.f;
#pragma unroll
        for (int j = 0; j < 6; j++) {
            float x = sv[tid * 6 + j];
            s += x; s2 += x * x;
        }
        red1[tid] = s; red2[tid] = s2;
    }
    __syncthreads();
    if (tid == 0) {
        float s = 0.f, s2 = 0.f;
#pragma unroll
        for (int j = 0; j < 32; j++) { s += red1[j]; s2 += red2[j]; }
        float m = s / DM;
        stat[0] = m;
        stat[1] = rsqrtf(s2 / DM - m * m + 1e-5f);
    }
    __syncthreads();
    sv[tid] = (sv[tid] - stat[0]) * stat[1] * nfw[tid] + nfb[tid];
    __syncthreads();
    if (tid < 2) {
        float a = hb[tid];
        for (int c = 0; c < DM; c++) a = fmaf(sv[c], hw[tid * DM + c], a);
        out[tid] = a;
    }
}

extern "C" void kernel_launch(void* const* d_in, const int* in_sizes, int n_in,
                              void* d_out, int out_size) {
    const float* x       = (const float*)d_in[0];
    const float* patch_w = (const float*)d_in[1];
    const float* patch_b = (const float*)d_in[2];
    const float* ln_w    = (const float*)d_in[3];
    const float* ln_b    = (const float*)d_in[4];
    const float* in_w    = (const float*)d_in[5];
    const float* cf_w    = (const float*)d_in[6];
    const float* cf_b    = (const float*)d_in[7];
    const float* xpf_w   = (const float*)d_in[8];
    const float* dtf_w   = (const float*)d_in[9];
    const float* dtf_b   = (const float*)d_in[10];
    const float* Alog_f  = (const float*)d_in[11];
    const float* D_f     = (const float*)d_in[12];
    const float* cbk_w   = (const float*)d_in[13];
    const float* cbk_b   = (const float*)d_in[14];
    const float* xpb_w   = (const float*)d_in[15];
    const float* dtb_w   = (const float*)d_in[16];
    const float* dtb_b   = (const float*)d_in[17];
    const float* Alog_b  = (const float*)d_in[18];
    const float* D_b     = (const float*)d_in[19];
    const float* out_w   = (const float*)d_in[20];
    const float* nf_w    = (const float*)d_in[21];
    const float* nf_b    = (const float*)d_in[22];
    const float* head_w  = (const float*)d_in[23];
    const float* head_b  = (const float*)d_in[24];
    float* out = (float*)d_out;

    k_setup<<<512, 256>>>(in_w, out_w, xpf_w, xpb_w, dtf_w, dtb_w,
                          Alog_f, Alog_b, D_f, D_b);
    k_gather<<<2048, 256>>>(x);
    k_patch_gemm<<<dim3(8, 3, 8), 256>>>(patch_w);
    k_patch_reduce<<<(LSEQ * DM + 255) / 256, 256>>>(patch_b);

    for (int l = 0; l < NLAY; l++) {
        k_layer_in<<<128, 256>>>(l, ln_w, ln_b);
        k_conv_proj<<<1024, 128>>>(l, cf_w, cf_b, cbk_w, cbk_b, dtf_b, dtb_b);
        k_scan_local<<<128, 192>>>(l);
        k_scan_apply<<<128, 192>>>(l);
        k_out<<<128, 256>>>(l);
    }
    k_final<<<1, 192>>>(nf_w, nf_b, head_w, head_b, out);
}

// round 8
// speedup vs baseline: 1.3080x; 1.3080x over previous
#include <cuda_runtime.h>
#include <cuda_bf16.h>
#include <math.h>

#define LSEQ 512
#define DM   192
#define DI   384
#define NS   16
#define RK   12
#define XO   44      // RK + 2*NS
#define NLAY 24
#define NCH  32
#define CS   16      // LSEQ / NCH
#define GRID 148

// ---------------- scratch (static device globals; no runtime allocation) ----------------
__device__ float g_hidden[LSEQ * DM];
__device__ float g_resid[2][LSEQ * DM];          // ping-pong
__device__ float g_xz[LSEQ * 2 * DI];
__device__ float g_u[2][LSEQ * DI];
__device__ float g_du[2][LSEQ * DI];
__device__ float g_dtv[2][LSEQ * DI];
__device__ float g_rex[2][LSEQ * DI];
__device__ float g_z[2][LSEQ * DI];
__device__ float g_Bm[2][LSEQ * NS];
__device__ float g_Cm[2][LSEQ * NS];
__device__ float g_PA[2][NCH * NS * DI];
__device__ float g_HE[2][NCH * NS * DI];
__device__ float g_y[2][LSEQ * DI];
// patch-embed scratch
__device__ float g_xpatch[LSEQ * 4096];
__device__ float g_ppart[8 * LSEQ * DM];
// preprocessed weights
__device__ float g_inT[NLAY * DM * 2 * DI];      // [l][k][o]
__device__ float g_outT[NLAY * DI * DM];         // [l][d][c]
__device__ float g_xpT[2][NLAY * DI * XO];       // [l][d][o]
__device__ float g_dtT[2][NLAY * RK * DI];       // [l][r][d]
__device__ float g_base[2][NLAY * DI];           // A0 = -exp(Alog[...,0])
__device__ float g_delta[2][NLAY * NS * DI];     // An - (n+1)*A0, [l][n][d]
__device__ float g_Dva[2][NLAY * DI];
// software grid barrier state (reset by k_setup_misc each replay)
__device__ unsigned g_cnt;
__device__ volatile unsigned g_epoch;

// ---------------- software grid barrier (grid must be <= 148, all resident) ----------------
__device__ __forceinline__ void gbar(unsigned e) {
    __syncthreads();
    if (threadIdx.x == 0) {
        __threadfence();
        unsigned prev = atomicAdd(&g_cnt, 1u);
        if (prev == e * GRID - 1u) {
            g_epoch = e;
        } else {
            while (g_epoch < e) { }
        }
    }
    __syncthreads();
}

// ---------------- setup A: coalesced tiled transposes of in_w / out_w ----------------
// grid 5184 blocks, 256 threads
__global__ void k_setup_w(const float* __restrict__ in_w, const float* __restrict__ out_w) {
    __shared__ float tile[32][33];
    int b = blockIdx.x;
    int tx = threadIdx.x & 31, ty = threadIdx.x >> 5;  // 8 rows per pass
    if (b < 3456) {
        // in_w (24, 768, 192) -> g_inT [l][k][o]; 24 o-tiles x 6 k-tiles per layer
        int l = b / 144; int r = b % 144; int ot = r / 6; int kt = r % 6;
        const float* src = in_w + (size_t)l * 768 * 192;
        float* dst = g_inT + (size_t)l * 192 * 768;
        int o0 = ot * 32, k0 = kt * 32;
        for (int rr = ty; rr < 32; rr += 8)
            tile[rr][tx] = src[(size_t)(o0 + rr) * 192 + k0 + tx];
        __syncthreads();
        for (int rr = ty; rr < 32; rr += 8)
            dst[(size_t)(k0 + rr) * 768 + o0 + tx] = tile[tx][rr];
    } else {
        // out_w (24, 192, 384) -> g_outT [l][d][c]; 6 c-tiles x 12 d-tiles per layer
        b -= 3456;
        int l = b / 72; int r = b % 72; int ct = r / 12; int dt = r % 12;
        const float* src = out_w + (size_t)l * 192 * 384;
        float* dst = g_outT + (size_t)l * 384 * 192;
        int c0 = ct * 32, d0 = dt * 32;
        for (int rr = ty; rr < 32; rr += 8)
            tile[rr][tx] = src[(size_t)(c0 + rr) * 384 + d0 + tx];
        __syncthreads();
        for (int rr = ty; rr < 32; rr += 8)
            dst[(size_t)(d0 + rr) * 192 + c0 + tx] = tile[tx][rr];
    }
}

// ---------------- setup B: small transposes + A-derived + zero resid + barrier reset ----------------
__global__ void k_setup_misc(const float* __restrict__ xpf, const float* __restrict__ xpb,
                             const float* __restrict__ dtfw, const float* __restrict__ dtbw,
                             const float* __restrict__ Alog_f, const float* __restrict__ Alog_b,
                             const float* __restrict__ D_f, const float* __restrict__ D_b) {
    int tid = blockIdx.x * blockDim.x + threadIdx.x;
    int nth = gridDim.x * blockDim.x;
    if (tid == 0) { g_cnt = 0; g_epoch = 0; }
    // xp (24,44,384) -> [l][d][o]
    for (int i = tid; i < NLAY * XO * DI; i += nth) {
        int l = i / (XO * DI); int r = i % (XO * DI); int o = r / DI; int d = r % DI;
        g_xpT[0][(l * DI + d) * XO + o] = xpf[i];
        g_xpT[1][(l * DI + d) * XO + o] = xpb[i];
    }
    // dt_w (24,384,12) -> [l][r][d]
    for (int i = tid; i < NLAY * DI * RK; i += nth) {
        int l = i / (DI * RK); int r2 = i % (DI * RK); int d = r2 / RK; int rr = r2 % RK;
        g_dtT[0][(l * RK + rr) * DI + d] = dtfw[i];
        g_dtT[1][(l * RK + rr) * DI + d] = dtbw[i];
    }
    // A-derived per (l,d)
    for (int i = tid; i < NLAY * DI; i += nth) {
        int l = i / DI; int d = i % DI;
        for (int dir = 0; dir < 2; dir++) {
            const float* Alog = dir ? Alog_b : Alog_f;
            float A0 = -expf(Alog[i * NS + 0]);
            g_base[dir][i] = A0;
            for (int n = 0; n < NS; n++) {
                float An = -expf(Alog[i * NS + n]);
                g_delta[dir][(l * NS + n) * DI + d] = An - (float)(n + 1) * A0;
            }
        }
        g_Dva[0][i] = D_f[i];
        g_Dva[1][i] = D_b[i];
    }
    for (int i = tid; i < LSEQ * DM; i += nth) g_resid[0][i] = 0.f;
}

// ---------------- patch embed: gather 16^3 patches -> [512][4096] ----------------
__global__ void k_gather(const float* __restrict__ x) {
    int i = blockIdx.x * blockDim.x + threadIdx.x;
    int nth = gridDim.x * blockDim.x;
    for (; i < LSEQ * 4096; i += nth) {
        int p = i >> 12;
        int k = i & 4095;
        int pz = p >> 6, py = (p >> 3) & 7, px = p & 7;
        int dz = k >> 8, dy = (k >> 4) & 15, dx = k & 15;
        size_t src = ((size_t)(pz * 16 + dz) * 128 + (py * 16 + dy)) * 128 + (px * 16 + dx);
        g_xpatch[i] = x[src];
    }
}

// ---------------- patch embed: split-K GEMM [512,4096]@[4096,192] ----------------
__global__ void k_patch_gemm(const float* __restrict__ pw) {
    __shared__ float sA[64][65];
    __shared__ float sB[64][65];
    int p0 = blockIdx.x * 64;
    int c0 = blockIdx.y * 64;
    int ks = blockIdx.z;
    int tid = threadIdx.x;
    int tr = tid >> 4, tc = tid & 15;
    float acc[4][4] = {};
    for (int kt = 0; kt < 8; kt++) {
        int kb = ks * 512 + kt * 64;
        int kk = tid & 63;
        int r0 = tid >> 6;
        for (int r = r0; r < 64; r += 4) {
            sA[r][kk] = g_xpatch[(size_t)(p0 + r) * 4096 + kb + kk];
            sB[kk][r] = pw[(size_t)(c0 + r) * 4096 + kb + kk];
        }
        __syncthreads();
        for (int q = 0; q < 64; q++) {
            float a[4], b[4];
#pragma unroll
            for (int i = 0; i < 4; i++) a[i] = sA[tr * 4 + i][q];
#pragma unroll
            for (int j = 0; j < 4; j++) b[j] = sB[q][tc * 4 + j];
#pragma unroll
            for (int i = 0; i < 4; i++)
#pragma unroll
                for (int j = 0; j < 4; j++)
                    acc[i][j] = fmaf(a[i], b[j], acc[i][j]);
        }
        __syncthreads();
    }
#pragma unroll
    for (int i = 0; i < 4; i++)
#pragma unroll
        for (int j = 0; j < 4; j++)
            g_ppart[((size_t)ks * LSEQ + p0 + tr * 4 + i) * DM + c0 + tc * 4 + j] = acc[i][j];
}

__global__ void k_patch_reduce(const float* __restrict__ pb) {
    int i = blockIdx.x * blockDim.x + threadIdx.x;
    if (i >= LSEQ * DM) return;
    int c = i % DM;
    float s = pb[c];
#pragma unroll
    for (int ks = 0; ks < 8; ks++) s += g_ppart[(size_t)ks * LSEQ * DM + i];
    g_hidden[i] = s;
}

// ---------------- THE persistent kernel: all 24 layers + final head ----------------
// grid exactly 148 blocks x 256 threads. Cross-block activation reads use __ldcg
// (L2-only) because L1 persists within this launch and is not coherent.
__global__ void __launch_bounds__(256) k_mamba(
    const float* __restrict__ ln_w, const float* __restrict__ ln_b,
    const float* __restrict__ cfw, const float* __restrict__ cfb,
    const float* __restrict__ cbw, const float* __restrict__ cbb,
    const float* __restrict__ dtbf, const float* __restrict__ dtbb,
    const float* __restrict__ nfw, const float* __restrict__ nfb,
    const float* __restrict__ hw, const float* __restrict__ hb,
    float* __restrict__ out)
{
    __shared__ float sm[3720];
    const int bid = blockIdx.x;
    const int tid = threadIdx.x;
    unsigned ep = 0;

    for (int l = 0; l < NLAY; l++) {
        // ===== phase IN: residual + LN + inproj GEMM (128 virtual blocks) =====
        {
            float* shn  = sm;            // 16*192
            float* sr1  = sm + 3072;     // 256
            float* sr2  = sm + 3328;     // 256
            float* stat = sm + 3584;     // 32
            int rb = l & 1;
            const float* rsrc = g_resid[rb];
            float* rdst = g_resid[rb ^ 1];
            for (int vb = bid; vb < 128; vb += GRID) {
                int tg = vb & 31, og = vb >> 5;
                int t0 = tg * 16;
                for (int i = tid; i < 16 * DM; i += 256) {
                    int tt = i / DM, c = i % DM;
                    float r = __ldcg(&rsrc[(t0 + tt) * DM + c]) + __ldcg(&g_hidden[(t0 + tt) * DM + c]);
                    shn[i] = r;
                    if (og == 0) rdst[(t0 + tt) * DM + c] = r;
                }
                __syncthreads();
                {
                    int tt = tid >> 4, seg = tid & 15;
                    float s = 0.f, s2 = 0.f;
#pragma unroll
                    for (int j = 0; j < 12; j++) {
                        float v = shn[tt * DM + seg * 12 + j];
                        s += v; s2 += v * v;
                    }
                    sr1[tt * 16 + seg] = s; sr2[tt * 16 + seg] = s2;
                }
                __syncthreads();
                if (tid < 16) {
                    float s = 0.f, s2 = 0.f;
#pragma unroll
                    for (int j = 0; j < 16; j++) { s += sr1[tid * 16 + j]; s2 += sr2[tid * 16 + j]; }
                    float m = s / DM;
                    stat[tid * 2] = m;
                    stat[tid * 2 + 1] = rsqrtf(s2 / DM - m * m + 1e-5f);
                }
                __syncthreads();
                for (int i = tid; i < 16 * DM; i += 256) {
                    int tt = i / DM, c = i % DM;
                    shn[i] = (shn[i] - stat[tt * 2]) * stat[tt * 2 + 1] * ln_w[l * DM + c] + ln_b[l * DM + c];
                }
                __syncthreads();
                int o64 = tid & 63;
                int ti = tid >> 6;
                const float* wbase = g_inT + (size_t)(l * DM) * 768 + og * 192 + o64;
                float a0[4] = {}, a1[4] = {}, a2[4] = {};
                for (int k = 0; k < DM; k++) {
                    const float* wk = wbase + (size_t)k * 768;
                    float w0 = wk[0], w1 = wk[64], w2 = wk[128];
#pragma unroll
                    for (int i2 = 0; i2 < 4; i2++) {
                        float xv = shn[(ti * 4 + i2) * DM + k];
                        a0[i2] = fmaf(xv, w0, a0[i2]);
                        a1[i2] = fmaf(xv, w1, a1[i2]);
                        a2[i2] = fmaf(xv, w2, a2[i2]);
                    }
                }
#pragma unroll
                for (int i2 = 0; i2 < 4; i2++) {
                    int t = t0 + ti * 4 + i2;
                    int ob = og * 192 + o64;
                    g_xz[t * 768 + ob] = a0[i2];
                    g_xz[t * 768 + ob + 64] = a1[i2];
                    g_xz[t * 768 + ob + 128] = a2[i2];
                }
                __syncthreads();
            }
        }
        gbar(++ep);

        // ===== phase CONV: conv + silu + xproj + dtproj + rexp (1024 virtual) =====
        {
            float* su    = sm;          // 384
            float* spart = sm + 384;    // 176
            float* sdbl  = sm + 560;    // 44
            for (int vb = bid; vb < 1024; vb += GRID) {
                int dir = vb >> 9;
                int t = vb & 511;
                int s = dir ? (LSEQ - 1 - t) : t;
                const float* cw = dir ? cbw : cfw;
                const float* cb = dir ? cbb : cfb;
                const float* dtb = dir ? dtbb : dtbf;
                for (int d = tid; d < DI; d += 256) {
                    float acc = cb[l * DI + d];
#pragma unroll
                    for (int j = 0; j < 4; j++) {
                        int ts = t - 3 + j;
                        if (ts >= 0) {
                            int orig = dir ? (LSEQ - 1 - ts) : ts;
                            acc = fmaf(__ldcg(&g_xz[orig * 768 + d]), cw[(l * DI + d) * 4 + j], acc);
                        }
                    }
                    float u = acc / (1.f + __expf(-acc));
                    su[d] = u;
                    g_u[dir][t * DI + d] = u;
                    g_z[dir][t * DI + d] = __ldcg(&g_xz[s * 768 + DI + d]);
                }
                __syncthreads();
                if (tid < 176) {
                    int q = tid / XO;
                    int o = tid - q * XO;
                    const float* xp = g_xpT[dir] + (size_t)(l * DI) * XO + o;
                    float acc = 0.f;
                    int d0 = q * 96;
#pragma unroll 4
                    for (int d = d0; d < d0 + 96; d++) acc = fmaf(su[d], xp[(size_t)d * XO], acc);
                    spart[tid] = acc;
                }
                __syncthreads();
                if (tid < XO) sdbl[tid] = spart[tid] + spart[XO + tid] + spart[2 * XO + tid] + spart[3 * XO + tid];
                __syncthreads();
                if (tid < NS) {
                    g_Bm[dir][t * NS + tid] = sdbl[RK + tid];
                    g_Cm[dir][t * NS + tid] = sdbl[RK + NS + tid];
                }
                for (int d = tid; d < DI; d += 256) {
                    float a = dtb[l * DI + d];
                    const float* dw = g_dtT[dir] + (size_t)(l * RK) * DI + d;
#pragma unroll
                    for (int r = 0; r < RK; r++) a = fmaf(sdbl[r], dw[(size_t)r * DI], a);
                    float dt = (a > 15.f) ? a : log1pf(__expf(a));
                    g_dtv[dir][t * DI + d] = dt;
                    g_du[dir][t * DI + d] = dt * su[d];
                    g_rex[dir][t * DI + d] = __expf(dt * g_base[dir][l * DI + d]);
                }
                __syncthreads();
            }
        }
        gbar(++ep);

        // ===== phase LOCAL: chunk-local scan -> carries (128 virtual) =====
        {
            float* sB = sm;  // 256
            for (int vb = bid; vb < 128; vb += GRID) {
                int dir = vb & 1;
                int c = (vb >> 1) & 31;
                int dh = vb >> 6;
                for (int i = tid; i < CS * NS; i += 256) sB[i] = __ldcg(&g_Bm[dir][c * CS * NS + i]);
                __syncthreads();
                if (tid < 192) {
                    int d = dh * 192 + tid;
                    float delta[NS];
#pragma unroll
                    for (int n = 0; n < NS; n++) delta[n] = g_delta[dir][(l * NS + n) * DI + d];
                    float h[NS], pa[NS];
#pragma unroll
                    for (int n = 0; n < NS; n++) { h[n] = 0.f; pa[n] = 1.f; }
                    for (int i = 0; i < CS; i++) {
                        int tg = c * CS + i;
                        float du = __ldcg(&g_du[dir][tg * DI + d]);
                        float r  = __ldcg(&g_rex[dir][tg * DI + d]);
                        float dt = __ldcg(&g_dtv[dir][tg * DI + d]);
                        float p = 1.f;
#pragma unroll
                        for (int n = 0; n < NS; n++) {
                            p *= r;
                            float dA = p * fmaf(dt, delta[n], 1.f);
                            pa[n] *= dA;
                            h[n] = fmaf(dA, h[n], du * sB[i * NS + n]);
                        }
                    }
#pragma unroll
                    for (int n = 0; n < NS; n++) {
                        g_PA[dir][(c * NS + n) * DI + d] = pa[n];
                        g_HE[dir][(c * NS + n) * DI + d] = h[n];
                    }
                }
                __syncthreads();
            }
        }
        gbar(++ep);

        // ===== phase APPLY: carry combine + apply + gate (128 virtual) =====
        {
            float* sB = sm;        // 256
            float* sC = sm + 256;  // 256
            for (int vb = bid; vb < 128; vb += GRID) {
                int dir = vb & 1;
                int c = (vb >> 1) & 31;
                int dh = vb >> 6;
                for (int i = tid; i < CS * NS; i += 256) {
                    sB[i] = __ldcg(&g_Bm[dir][c * CS * NS + i]);
                    sC[i] = __ldcg(&g_Cm[dir][c * CS * NS + i]);
                }
                __syncthreads();
                if (tid < 192) {
                    int d = dh * 192 + tid;
                    float delta[NS];
#pragma unroll
                    for (int n = 0; n < NS; n++) delta[n] = g_delta[dir][(l * NS + n) * DI + d];
                    float Dv = g_Dva[dir][l * DI + d];
                    float h[NS];
#pragma unroll
                    for (int n = 0; n < NS; n++) h[n] = 0.f;
                    for (int cp = 0; cp < c; cp++) {
#pragma unroll
                        for (int n = 0; n < NS; n++)
                            h[n] = fmaf(__ldcg(&g_PA[dir][(cp * NS + n) * DI + d]), h[n],
                                        __ldcg(&g_HE[dir][(cp * NS + n) * DI + d]));
                    }
                    for (int i = 0; i < CS; i++) {
                        int tg = c * CS + i;
                        float du = __ldcg(&g_du[dir][tg * DI + d]);
                        float r  = __ldcg(&g_rex[dir][tg * DI + d]);
                        float dt = __ldcg(&g_dtv[dir][tg * DI + d]);
                        float u  = __ldcg(&g_u[dir][tg * DI + d]);
                        float z  = __ldcg(&g_z[dir][tg * DI + d]);
                        float p = 1.f, y = 0.f;
#pragma unroll
                        for (int n = 0; n < NS; n++) {
                            p *= r;
                            float dA = p * fmaf(dt, delta[n], 1.f);
                            h[n] = fmaf(dA, h[n], du * sB[i * NS + n]);
                            y = fmaf(h[n], sC[i * NS + n], y);
                        }
                        y = fmaf(u, Dv, y);
                        float sg = z / (1.f + __expf(-z));
                        g_y[dir][tg * DI + d] = y * sg;
                    }
                }
                __syncthreads();
            }
        }
        gbar(++ep);

        // ===== phase OUT: (yf + flip(yb)) @ out_w^T -> hidden (128 virtual) =====
        {
            float* sy = sm;  // 4*384
            for (int vb = bid; vb < 128; vb += GRID) {
                int t0 = vb * 4;
                for (int i = tid; i < 4 * DI; i += 256) {
                    int tt = i / DI, d = i % DI;
                    sy[i] = __ldcg(&g_y[0][(t0 + tt) * DI + d]) +
                            __ldcg(&g_y[1][(LSEQ - 1 - (t0 + tt)) * DI + d]);
                }
                __syncthreads();
                if (tid < DM) {
                    float acc[4] = {};
                    const float* wb = g_outT + (size_t)(l * DI) * DM + tid;
                    for (int k = 0; k < DI; k++) {
                        float w = wb[(size_t)k * DM];
#pragma unroll
                        for (int tt = 0; tt < 4; tt++) acc[tt] = fmaf(sy[tt * DI + k], w, acc[tt]);
                    }
#pragma unroll
                    for (int tt = 0; tt < 4; tt++) g_hidden[(t0 + tt) * DM + tid] = acc[tt];
                }
                __syncthreads();
            }
        }
        gbar(++ep);
    }

    // ===== final: LN(resid + hidden)[511] @ head (block 0) =====
    if (bid == 0) {
        float* sv   = sm;        // 192
        float* red1 = sm + 192;  // 32
        float* red2 = sm + 224;  // 32
        float* st   = sm + 256;  // 2
        if (tid < DM)
            sv[tid] = __ldcg(&g_resid[0][511 * DM + tid]) + __ldcg(&g_hidden[511 * DM + tid]);
        __syncthreads();
        if (tid < 32) {
            float s = 0.f, s2 = 0.f;
#pragma unroll
            for (int j = 0; j < 6; j++) {
                float x = sv[tid * 6 + j];
                s += x; s2 += x * x;
            }
            red1[tid] = s; red2[tid] = s2;
        }
        __syncthreads();
        if (tid == 0) {
            float s = 0.f, s2 = 0.f;
#pragma unroll
            for (int j = 0; j < 32; j++) { s += red1[j]; s2 += red2[j]; }
            float m = s / DM;
            st[0] = m;
            st[1] = rsqrtf(s2 / DM - m * m + 1e-5f);
        }
        __syncthreads();
        if (tid < DM) sv[tid] = (sv[tid] - st[0]) * st[1] * nfw[tid] + nfb[tid];
        __syncthreads();
        if (tid < 2) {
            float a = hb[tid];
            for (int c = 0; c < DM; c++) a = fmaf(sv[c], hw[tid * DM + c], a);
            out[tid] = a;
        }
    }
}

extern "C" void kernel_launch(void* const* d_in, const int* in_sizes, int n_in,
                              void* d_out, int out_size) {
    const float* x       = (const float*)d_in[0];
    const float* patch_w = (const float*)d_in[1];
    const float* patch_b = (const float*)d_in[2];
    const float* ln_w    = (const float*)d_in[3];
    const float* ln_b    = (const float*)d_in[4];
    const float* in_w    = (const float*)d_in[5];
    const float* cf_w    = (const float*)d_in[6];
    const float* cf_b    = (const float*)d_in[7];
    const float* xpf_w   = (const float*)d_in[8];
    const float* dtf_w   = (const float*)d_in[9];
    const float* dtf_b   = (const float*)d_in[10];
    const float* Alog_f  = (const float*)d_in[11];
    const float* D_f     = (const float*)d_in[12];
    const float* cbk_w   = (const float*)d_in[13];
    const float* cbk_b   = (const float*)d_in[14];
    const float* xpb_w   = (const float*)d_in[15];
    const float* dtb_w   = (const float*)d_in[16];
    const float* dtb_b   = (const float*)d_in[17];
    const float* Alog_b  = (const float*)d_in[18];
    const float* D_b     = (const float*)d_in[19];
    const float* out_w   = (const float*)d_in[20];
    const float* nf_w    = (const float*)d_in[21];
    const float* nf_b    = (const float*)d_in[22];
    const float* head_w  = (const float*)d_in[23];
    const float* head_b  = (const float*)d_in[24];
    float* out = (float*)d_out;

    k_setup_w<<<5184, 256>>>(in_w, out_w);                                   // launch 0
    k_setup_misc<<<256, 256>>>(xpf_w, xpb_w, dtf_w, dtb_w,
                               Alog_f, Alog_b, D_f, D_b);                    // launch 1
    k_gather<<<2048, 256>>>(x);                                              // launch 2
    k_patch_gemm<<<dim3(8, 3, 8), 256>>>(patch_w);                           // launch 3
    k_patch_reduce<<<(LSEQ * DM + 255) / 256, 256>>>(patch_b);               // launch 4
    k_mamba<<<GRID, 256>>>(ln_w, ln_b, cf_w, cf_b, cbk_w, cbk_b,
                           dtf_b, dtb_b, nf_w, nf_b, head_w, head_b, out);   // launch 5
}